// round 3
// baseline (speedup 1.0000x reference)
#include <cuda_runtime.h>

#define NN   200000
#define NE   800000
#define FIN  32
#define HID  128
#define NG   8192
#define NOUT 5

// ---------------- scratch (device globals; no allocations allowed) ----------
__device__ float g_dinv[NN];
__device__ float g_agg[(size_t)NN * HID];   // aggregation output
__device__ float g_h[(size_t)NN * HID];     // post-layer activations
__device__ float g_pool[NG * HID];
__device__ float g_cnt[NG];
__device__ float g_scale[3 * HID];
__device__ float g_shift[3 * HID];

// vectorized global reduction (sm_90+)
__device__ __forceinline__ void red_add_v4(float* addr, float4 v) {
    asm volatile("red.global.add.v4.f32 [%0], {%1,%2,%3,%4};"
                 :: "l"(addr), "f"(v.x), "f"(v.y), "f"(v.z), "f"(v.w)
                 : "memory");
}

// ---------------- init / degree ---------------------------------------------
__global__ void k_zero() {
    int i = blockIdx.x * blockDim.x + threadIdx.x;
    if (i < NN)        g_dinv[i] = 0.f;
    if (i < NG * HID)  g_pool[i] = 0.f;
    if (i < NG)        g_cnt[i]  = 0.f;
}

__global__ void k_count(const int* __restrict__ col) {
    int e = blockIdx.x * blockDim.x + threadIdx.x;
    if (e < NE) atomicAdd(&g_dinv[col[e]], 1.0f);
}

__global__ void k_dinv() {
    int v = blockIdx.x * blockDim.x + threadIdx.x;
    if (v < NN) g_dinv[v] = rsqrtf(g_dinv[v] + 1.0f);   // +1 self-loop
}

// fold bias + batchnorm into y = h*scale + shift
__global__ void k_affine(const float* __restrict__ b, const float* __restrict__ ga,
                         const float* __restrict__ be, const float* __restrict__ me,
                         const float* __restrict__ va, int layer) {
    int c = threadIdx.x;
    if (c < HID) {
        float s = ga[c] * rsqrtf(va[c] + 1e-5f);
        g_scale[layer * HID + c] = s;
        g_shift[layer * HID + c] = (b[c] - me[c]) * s + be[c];
    }
}

// ---------------- aggregation: agg[v] = dinv[v]^2 * in[v] + sum_e dinv[r]dinv[v] in[r]
template<int D, bool FROM_GH>
__global__ void k_agg_init(const float* __restrict__ xin) {
    const int Q = D / 4;
    int i = blockIdx.x * blockDim.x + threadIdx.x;
    if (i >= NN * Q) return;
    int v = i / Q;
    const float4* in4 = FROM_GH ? (const float4*)g_h : (const float4*)xin;
    float dv = g_dinv[v];
    float c = dv * dv;
    float4 x = in4[i];
    x.x *= c; x.y *= c; x.z *= c; x.w *= c;
    ((float4*)g_agg)[i] = x;
}

template<int D, bool FROM_GH>
__global__ void k_agg_edges(const float* __restrict__ xin,
                            const int* __restrict__ row, const int* __restrict__ col) {
    const int Q = D / 4;
    int i = blockIdx.x * blockDim.x + threadIdx.x;
    if (i >= NE * Q) return;
    int e = i / Q;
    int q = i - e * Q;
    int r = row[e], c = col[e];
    float coef = g_dinv[r] * g_dinv[c];
    const float4* in4 = FROM_GH ? (const float4*)g_h : (const float4*)xin;
    float4 v = in4[(size_t)r * Q + q];
    v.x *= coef; v.y *= coef; v.z *= coef; v.w *= coef;
    red_add_v4(&g_agg[(size_t)c * D + q * 4], v);
}

// ---------------- GEMM: g_h = relu(scale * (g_agg @ W) + shift) --------------
// A: [NN, K] row-major (g_agg), W: [K, 128] row-major. BM=64, BN=128, BK=32.
// 256 threads, each computes 8x4 micro-tile. scale/shift indexed by layer
// INSIDE device code (host must never take a __device__ symbol's address).
template<int K>
__global__ __launch_bounds__(256)
void k_gemm(const float* __restrict__ W, int layer) {
    __shared__ float sAt[32][68];     // [k][row], padded
    __shared__ float sB[32][128];     // [k][col]

    const int tid = threadIdx.x;
    const int tr  = tid >> 5;         // 0..7  row group
    const int tc  = tid & 31;         // 0..31 col group
    const int row0 = blockIdx.x * 64;

    float acc[8][4];
#pragma unroll
    for (int m = 0; m < 8; m++)
#pragma unroll
        for (int n = 0; n < 4; n++) acc[m][n] = 0.f;

    for (int k0 = 0; k0 < K; k0 += 32) {
        // A tile -> transposed shared
#pragma unroll
        for (int i = 0; i < 2; i++) {
            int l  = tid + 256 * i;       // 0..511 float4s, 8 per row
            int r  = l >> 3;
            int k4 = (l & 7) * 4;
            float4 a = *(const float4*)&g_agg[(size_t)(row0 + r) * K + k0 + k4];
            sAt[k4 + 0][r] = a.x; sAt[k4 + 1][r] = a.y;
            sAt[k4 + 2][r] = a.z; sAt[k4 + 3][r] = a.w;
        }
        // W tile
#pragma unroll
        for (int i = 0; i < 4; i++) {
            int f  = tid + 256 * i;       // 0..1023 float4s, 32 per row
            int k  = f >> 5;
            int c4 = (f & 31) * 4;
            *(float4*)&sB[k][c4] = *(const float4*)&W[(size_t)(k0 + k) * 128 + c4];
        }
        __syncthreads();

#pragma unroll
        for (int k = 0; k < 32; k++) {
            float4 a0 = *(const float4*)&sAt[k][tr * 8];
            float4 a1 = *(const float4*)&sAt[k][tr * 8 + 4];
            float4 b  = *(const float4*)&sB[k][tc * 4];
            float av[8] = {a0.x, a0.y, a0.z, a0.w, a1.x, a1.y, a1.z, a1.w};
            float bv[4] = {b.x, b.y, b.z, b.w};
#pragma unroll
            for (int m = 0; m < 8; m++)
#pragma unroll
                for (int n = 0; n < 4; n++)
                    acc[m][n] += av[m] * bv[n];
        }
        __syncthreads();
    }

    int colb = tc * 4;
    float4 s = *(const float4*)&g_scale[layer * HID + colb];
    float4 t = *(const float4*)&g_shift[layer * HID + colb];
#pragma unroll
    for (int m = 0; m < 8; m++) {
        int rr = row0 + tr * 8 + m;
        float4 o;
        o.x = fmaxf(acc[m][0] * s.x + t.x, 0.f);
        o.y = fmaxf(acc[m][1] * s.y + t.y, 0.f);
        o.z = fmaxf(acc[m][2] * s.z + t.z, 0.f);
        o.w = fmaxf(acc[m][3] * s.w + t.w, 0.f);
        *(float4*)&g_h[(size_t)rr * 128 + colb] = o;
    }
}

// ---------------- pooling + output ------------------------------------------
__global__ void k_pool(const int* __restrict__ batch) {
    int i = blockIdx.x * blockDim.x + threadIdx.x;
    if (i >= NN * 32) return;
    int v = i >> 5, q = i & 31;
    int b = batch[v];
    float4 h = ((const float4*)g_h)[i];
    red_add_v4(&g_pool[b * HID + q * 4], h);
    if (q == 0) atomicAdd(&g_cnt[b], 1.0f);
}

__global__ void k_out(const float* __restrict__ Wout, const float* __restrict__ bout,
                      float* __restrict__ out) {
    int i = blockIdx.x * blockDim.x + threadIdx.x;
    if (i >= NG * NOUT) return;
    int g = i / NOUT, o = i - g * NOUT;
    float inv = 1.0f / fmaxf(g_cnt[g], 1.0f);
    const float* p = &g_pool[g * HID];
    float s = 0.f;
#pragma unroll 8
    for (int k = 0; k < HID; k++) s += p[k] * Wout[k * NOUT + o];
    out[i] = s * inv + bout[o];
}

// ---------------- launch -----------------------------------------------------
extern "C" void kernel_launch(void* const* d_in, const int* in_sizes, int n_in,
                              void* d_out, int out_size) {
    const float* x     = (const float*)d_in[0];
    const int*   ei    = (const int*)d_in[1];
    const int*   batch = (const int*)d_in[2];
    const float* W0 = (const float*)d_in[3];
    const float* b0 = (const float*)d_in[4];
    const float* ga0 = (const float*)d_in[5];
    const float* be0 = (const float*)d_in[6];
    const float* me0 = (const float*)d_in[7];
    const float* va0 = (const float*)d_in[8];
    const float* W1 = (const float*)d_in[9];
    const float* b1 = (const float*)d_in[10];
    const float* ga1 = (const float*)d_in[11];
    const float* be1 = (const float*)d_in[12];
    const float* me1 = (const float*)d_in[13];
    const float* va1 = (const float*)d_in[14];
    const float* W2 = (const float*)d_in[15];
    const float* b2 = (const float*)d_in[16];
    const float* ga2 = (const float*)d_in[17];
    const float* be2 = (const float*)d_in[18];
    const float* me2 = (const float*)d_in[19];
    const float* va2 = (const float*)d_in[20];
    const float* Wout = (const float*)d_in[21];
    const float* bout = (const float*)d_in[22];
    float* out = (float*)d_out;

    const int* row = ei;        // edge_index[0]
    const int* col = ei + NE;   // edge_index[1]

    k_zero<<<(NG * HID + 255) / 256, 256>>>();
    k_count<<<(NE + 255) / 256, 256>>>(col);
    k_dinv<<<(NN + 255) / 256, 256>>>();
    k_affine<<<1, 128>>>(b0, ga0, be0, me0, va0, 0);
    k_affine<<<1, 128>>>(b1, ga1, be1, me1, va1, 1);
    k_affine<<<1, 128>>>(b2, ga2, be2, me2, va2, 2);

    // layer 0: aggregate x (32 features), then GEMM K=32
    k_agg_init<FIN, false><<<(NN * (FIN / 4) + 255) / 256, 256>>>(x);
    k_agg_edges<FIN, false><<<(NE * (FIN / 4) + 255) / 256, 256>>>(x, row, col);
    k_gemm<FIN><<<NN / 64, 256>>>(W0, 0);

    // layer 1
    k_agg_init<HID, true><<<(NN * (HID / 4) + 255) / 256, 256>>>(nullptr);
    k_agg_edges<HID, true><<<(NE * (HID / 4) + 255) / 256, 256>>>(nullptr, row, col);
    k_gemm<HID><<<NN / 64, 256>>>(W1, 1);

    // layer 2
    k_agg_init<HID, true><<<(NN * (HID / 4) + 255) / 256, 256>>>(nullptr);
    k_agg_edges<HID, true><<<(NE * (HID / 4) + 255) / 256, 256>>>(nullptr, row, col);
    k_gemm<HID><<<NN / 64, 256>>>(W2, 2);

    // pool + output
    k_pool<<<(NN * 32 + 255) / 256, 256>>>(batch);
    k_out<<<(NG * NOUT + 255) / 256, 256>>>(Wout, bout, out);
}

// round 6
// speedup vs baseline: 1.1008x; 1.1008x over previous
#include <cuda_runtime.h>
#include <cstdint>

#define NN   200000
#define MPAD 200064          // 1563 * 128
#define NE   800000
#define FIN  32
#define HID  128
#define NG   8192
#define NOUT 5

// ---------------- scratch (device globals; no allocations allowed) ----------
__device__ float g_dinv[NN];
__device__ float g_agg[(size_t)MPAD * HID];
__device__ float g_h[(size_t)MPAD * HID];
__device__ float g_pool[NG * HID];
__device__ float g_cnt[NG];
__device__ float g_scale[3 * HID];
__device__ float g_shift[3 * HID];

// ---------------- helpers ----------------------------------------------------
__device__ __forceinline__ void red_add_v4(float* addr, float4 v) {
    asm volatile("red.global.add.v4.f32 [%0], {%1,%2,%3,%4};"
                 :: "l"(addr), "f"(v.x), "f"(v.y), "f"(v.z), "f"(v.w)
                 : "memory");
}

__device__ __forceinline__ float tf32f(float x) {
    uint32_t u;
    asm("cvt.rna.tf32.f32 %0, %1;" : "=r"(u) : "f"(x));
    return __uint_as_float(u);
}

__device__ __forceinline__ void mma_tf32(float* d, const uint32_t* a, const uint32_t* b) {
    asm volatile("mma.sync.aligned.m16n8k8.row.col.f32.tf32.tf32.f32 "
                 "{%0,%1,%2,%3}, {%4,%5,%6,%7}, {%8,%9}, {%0,%1,%2,%3};"
                 : "+f"(d[0]), "+f"(d[1]), "+f"(d[2]), "+f"(d[3])
                 : "r"(a[0]), "r"(a[1]), "r"(a[2]), "r"(a[3]),
                   "r"(b[0]), "r"(b[1]));
}

// ---------------- init / degree ---------------------------------------------
__global__ void k_zero() {
    int i = blockIdx.x * blockDim.x + threadIdx.x;
    if (i < NN)       g_dinv[i] = 0.f;
    if (i < NG * HID) g_pool[i] = 0.f;
    if (i < NG)       g_cnt[i]  = 0.f;
}

__global__ void k_count(const int* __restrict__ col) {
    int e = blockIdx.x * blockDim.x + threadIdx.x;
    if (e < NE) atomicAdd(&g_dinv[col[e]], 1.0f);
}

__global__ void k_dinv() {
    int v = blockIdx.x * blockDim.x + threadIdx.x;
    if (v < NN) g_dinv[v] = rsqrtf(g_dinv[v] + 1.0f);
}

__global__ void k_affine(const float* __restrict__ b, const float* __restrict__ ga,
                         const float* __restrict__ be, const float* __restrict__ me,
                         const float* __restrict__ va, int layer) {
    int c = threadIdx.x;
    if (c < HID) {
        float s = ga[c] * rsqrtf(va[c] + 1e-5f);
        g_scale[layer * HID + c] = s;
        g_shift[layer * HID + c] = (b[c] - me[c]) * s + be[c];
    }
}

// ---------------- aggregation ------------------------------------------------
template<int D, bool FROM_GH>
__global__ void k_agg_init(const float* __restrict__ xin) {
    const int Q = D / 4;
    int i = blockIdx.x * blockDim.x + threadIdx.x;
    if (i >= NN * Q) return;
    int v = i / Q;
    float dv = g_dinv[v];
    float c = dv * dv;
    float4 x = FROM_GH ? ((const float4*)g_h)[i] : ((const float4*)xin)[i];
    x.x *= c; x.y *= c; x.z *= c; x.w *= c;
    ((float4*)g_agg)[i] = x;
}

template<int D, bool FROM_GH>
__global__ void k_agg_edges(const float* __restrict__ xin,
                            const int* __restrict__ row, const int* __restrict__ col) {
    const int Q = D / 4;
    int i = blockIdx.x * blockDim.x + threadIdx.x;
    if (i >= NE * Q) return;
    int e = i / Q;
    int q = i - e * Q;
    int r = row[e], c = col[e];
    float coef = g_dinv[r] * g_dinv[c];
    const float4* in4 = FROM_GH ? (const float4*)g_h : (const float4*)xin;
    float4 v = in4[(size_t)r * Q + q];
    v.x *= coef; v.y *= coef; v.z *= coef; v.w *= coef;
    red_add_v4(&g_agg[(size_t)c * D + q * 4], v);
}

// ---------------- SIMT GEMM (layer 0, K=32) ---------------------------------
template<int K>
__global__ __launch_bounds__(256)
void k_gemm(const float* __restrict__ W, int layer) {
    __shared__ float sAt[32][68];
    __shared__ float sB[32][128];

    const int tid = threadIdx.x;
    const int tr  = tid >> 5;
    const int tc  = tid & 31;
    const int row0 = blockIdx.x * 64;

    float acc[8][4];
#pragma unroll
    for (int m = 0; m < 8; m++)
#pragma unroll
        for (int n = 0; n < 4; n++) acc[m][n] = 0.f;

    for (int k0 = 0; k0 < K; k0 += 32) {
#pragma unroll
        for (int i = 0; i < 2; i++) {
            int l  = tid + 256 * i;
            int r  = l >> 3;
            int k4 = (l & 7) * 4;
            float4 a = *(const float4*)&g_agg[(size_t)(row0 + r) * K + k0 + k4];
            sAt[k4 + 0][r] = a.x; sAt[k4 + 1][r] = a.y;
            sAt[k4 + 2][r] = a.z; sAt[k4 + 3][r] = a.w;
        }
#pragma unroll
        for (int i = 0; i < 4; i++) {
            int f  = tid + 256 * i;
            int k  = f >> 5;
            int c4 = (f & 31) * 4;
            *(float4*)&sB[k][c4] = *(const float4*)&W[(size_t)(k0 + k) * 128 + c4];
        }
        __syncthreads();

#pragma unroll
        for (int k = 0; k < 32; k++) {
            float4 a0 = *(const float4*)&sAt[k][tr * 8];
            float4 a1 = *(const float4*)&sAt[k][tr * 8 + 4];
            float4 b  = *(const float4*)&sB[k][tc * 4];
            float av[8] = {a0.x, a0.y, a0.z, a0.w, a1.x, a1.y, a1.z, a1.w};
            float bv[4] = {b.x, b.y, b.z, b.w};
#pragma unroll
            for (int m = 0; m < 8; m++)
#pragma unroll
                for (int n = 0; n < 4; n++)
                    acc[m][n] += av[m] * bv[n];
        }
        __syncthreads();
    }

    int colb = tc * 4;
    float4 s = *(const float4*)&g_scale[layer * HID + colb];
    float4 t = *(const float4*)&g_shift[layer * HID + colb];
#pragma unroll
    for (int m = 0; m < 8; m++) {
        int rr = row0 + tr * 8 + m;
        float4 o;
        o.x = fmaxf(acc[m][0] * s.x + t.x, 0.f);
        o.y = fmaxf(acc[m][1] * s.y + t.y, 0.f);
        o.z = fmaxf(acc[m][2] * s.z + t.z, 0.f);
        o.w = fmaxf(acc[m][3] * s.w + t.w, 0.f);
        *(float4*)&g_h[(size_t)rr * 128 + colb] = o;
    }
}

// ---------------- mma.sync tf32 GEMM (layers 1/2, K=128) ---------------------
// C[128,128] per CTA. 8 warps in 2x4; warp tile 64x32 via 4x4 m16n8k8 frags.
// 2-term tf32 split: a*b ~= ah*bh + al*bh + ah*bl  (error ~2^-21).
// SMEM: A [128][68] (pad->banks 4r+c distinct), B [64][136] (banks 8c+r distinct).
#define SA_STRIDE 68
#define SB_STRIDE 136
#define SM_A_FLOATS (128 * SA_STRIDE)
#define SM_B_FLOATS (64 * SB_STRIDE)
#define SM_MMA_BYTES ((SM_A_FLOATS + SM_B_FLOATS) * 4)

__global__ __launch_bounds__(256, 2)
void k_mma(const float* __restrict__ Wm, int layer) {
    extern __shared__ float smem[];
    float* sA = smem;                  // [128][68]
    float* sB = smem + SM_A_FLOATS;    // [64][136]

    const int tid = threadIdx.x;
    const int wid = tid >> 5;
    const int l   = tid & 31;
    const int wr  = wid >> 2;          // 0..1 : rows 64*wr
    const int wc  = wid & 3;           // 0..3 : cols 32*wc
    const size_t row0 = (size_t)blockIdx.x * 128;

    float acc[4][4][4];
#pragma unroll
    for (int mt = 0; mt < 4; mt++)
#pragma unroll
        for (int nt = 0; nt < 4; nt++)
#pragma unroll
            for (int r = 0; r < 4; r++) acc[mt][nt][r] = 0.f;

    const int lr = l >> 2;             // 0..7
    const int lc = l & 3;              // 0..3

    for (int kc = 0; kc < 2; kc++) {
        // load A chunk: 128 rows x 64 k
#pragma unroll
        for (int it = 0; it < 8; it++) {
            int idx = tid + it * 256;          // 0..2047 float4
            int r   = idx >> 4;
            int q4  = (idx & 15) * 4;
            float4 a = *(const float4*)&g_agg[(row0 + r) * HID + kc * 64 + q4];
            float* p = &sA[r * SA_STRIDE + q4];
            p[0] = a.x; p[1] = a.y; p[2] = a.z; p[3] = a.w;
        }
        // load B chunk: 64 k x 128 n  (W is [K,N] row-major == col-major B)
#pragma unroll
        for (int it = 0; it < 8; it++) {
            int idx = tid + it * 256;          // 0..2047 float4
            int k   = idx >> 5;
            int n4  = (idx & 31) * 4;
            float4 b = *(const float4*)&Wm[(size_t)(kc * 64 + k) * HID + n4];
            float* p = &sB[k * SB_STRIDE + n4];
            p[0] = b.x; p[1] = b.y; p[2] = b.z; p[3] = b.w;
        }
        __syncthreads();

#pragma unroll
        for (int ks = 0; ks < 8; ks++) {
            const int kk = ks * 8;
            // B fragments for the 4 n-tiles
            uint32_t bh[4][2], bl[4][2];
#pragma unroll
            for (int nt = 0; nt < 4; nt++) {
                int colp = wc * 32 + nt * 8 + lr;
                float b0 = sB[(kk + lc) * SB_STRIDE + colp];
                float b1 = sB[(kk + 4 + lc) * SB_STRIDE + colp];
                float h0 = tf32f(b0), h1 = tf32f(b1);
                bh[nt][0] = __float_as_uint(h0); bl[nt][0] = __float_as_uint(b0 - h0);
                bh[nt][1] = __float_as_uint(h1); bl[nt][1] = __float_as_uint(b1 - h1);
            }
#pragma unroll
            for (int mt = 0; mt < 4; mt++) {
                int rbase = wr * 64 + mt * 16 + lr;
                float a0 = sA[rbase * SA_STRIDE + kk + lc];
                float a1 = sA[(rbase + 8) * SA_STRIDE + kk + lc];
                float a2 = sA[rbase * SA_STRIDE + kk + 4 + lc];
                float a3 = sA[(rbase + 8) * SA_STRIDE + kk + 4 + lc];
                float h0 = tf32f(a0), h1 = tf32f(a1), h2 = tf32f(a2), h3 = tf32f(a3);
                uint32_t ah[4] = {__float_as_uint(h0), __float_as_uint(h1),
                                  __float_as_uint(h2), __float_as_uint(h3)};
                uint32_t al[4] = {__float_as_uint(a0 - h0), __float_as_uint(a1 - h1),
                                  __float_as_uint(a2 - h2), __float_as_uint(a3 - h3)};
#pragma unroll
                for (int nt = 0; nt < 4; nt++) {
                    mma_tf32(acc[mt][nt], ah, bh[nt]);
                    mma_tf32(acc[mt][nt], al, bh[nt]);
                    mma_tf32(acc[mt][nt], ah, bl[nt]);
                }
            }
        }
        __syncthreads();
    }

    // epilogue: fold BN/bias, ReLU, store float2 per c-pair
#pragma unroll
    for (int nt = 0; nt < 4; nt++) {
        int c = wc * 32 + nt * 8 + 2 * lc;
        float2 s = *(const float2*)&g_scale[layer * HID + c];
        float2 t = *(const float2*)&g_shift[layer * HID + c];
#pragma unroll
        for (int mt = 0; mt < 4; mt++) {
            size_t r = row0 + wr * 64 + mt * 16 + lr;
            float2 o0, o1;
            o0.x = fmaxf(acc[mt][nt][0] * s.x + t.x, 0.f);
            o0.y = fmaxf(acc[mt][nt][1] * s.y + t.y, 0.f);
            o1.x = fmaxf(acc[mt][nt][2] * s.x + t.x, 0.f);
            o1.y = fmaxf(acc[mt][nt][3] * s.y + t.y, 0.f);
            *(float2*)&g_h[r * HID + c]       = o0;
            *(float2*)&g_h[(r + 8) * HID + c] = o1;
        }
    }
}

// ---------------- pooling + output ------------------------------------------
__global__ void k_pool(const int* __restrict__ batch) {
    int i = blockIdx.x * blockDim.x + threadIdx.x;
    if (i >= NN * 32) return;
    int v = i >> 5, q = i & 31;
    int b = batch[v];
    float4 h = *(const float4*)&g_h[(size_t)v * HID + q * 4];
    red_add_v4(&g_pool[b * HID + q * 4], h);
    if (q == 0) atomicAdd(&g_cnt[b], 1.0f);
}

__global__ void k_out(const float* __restrict__ Wout, const float* __restrict__ bout,
                      float* __restrict__ out) {
    int i = blockIdx.x * blockDim.x + threadIdx.x;
    if (i >= NG * NOUT) return;
    int g = i / NOUT, o = i - g * NOUT;
    float inv = 1.0f / fmaxf(g_cnt[g], 1.0f);
    const float* p = &g_pool[g * HID];
    float s = 0.f;
#pragma unroll 8
    for (int k = 0; k < HID; k++) s += p[k] * Wout[k * NOUT + o];
    out[i] = s * inv + bout[o];
}

// ---------------- launch -----------------------------------------------------
extern "C" void kernel_launch(void* const* d_in, const int* in_sizes, int n_in,
                              void* d_out, int out_size) {
    const float* x     = (const float*)d_in[0];
    const int*   ei    = (const int*)d_in[1];
    const int*   batch = (const int*)d_in[2];
    const float* W0 = (const float*)d_in[3];
    const float* b0 = (const float*)d_in[4];
    const float* ga0 = (const float*)d_in[5];
    const float* be0 = (const float*)d_in[6];
    const float* me0 = (const float*)d_in[7];
    const float* va0 = (const float*)d_in[8];
    const float* W1 = (const float*)d_in[9];
    const float* b1 = (const float*)d_in[10];
    const float* ga1 = (const float*)d_in[11];
    const float* be1 = (const float*)d_in[12];
    const float* me1 = (const float*)d_in[13];
    const float* va1 = (const float*)d_in[14];
    const float* W2 = (const float*)d_in[15];
    const float* b2 = (const float*)d_in[16];
    const float* ga2 = (const float*)d_in[17];
    const float* be2 = (const float*)d_in[18];
    const float* me2 = (const float*)d_in[19];
    const float* va2 = (const float*)d_in[20];
    const float* Wout = (const float*)d_in[21];
    const float* bout = (const float*)d_in[22];
    float* out = (float*)d_out;

    const int* row = ei;
    const int* col = ei + NE;

    cudaFuncSetAttribute(k_mma, cudaFuncAttributeMaxDynamicSharedMemorySize, SM_MMA_BYTES);

    k_zero<<<(NG * HID + 255) / 256, 256>>>();
    k_count<<<(NE + 255) / 256, 256>>>(col);
    k_dinv<<<(NN + 255) / 256, 256>>>();
    k_affine<<<1, 128>>>(b0, ga0, be0, me0, va0, 0);
    k_affine<<<1, 128>>>(b1, ga1, be1, me1, va1, 1);
    k_affine<<<1, 128>>>(b2, ga2, be2, me2, va2, 2);

    // layer 0: aggregate x (32 features), SIMT GEMM K=32 over padded rows
    k_agg_init<FIN, false><<<(NN * (FIN / 4) + 255) / 256, 256>>>(x);
    k_agg_edges<FIN, false><<<(NE * (FIN / 4) + 255) / 256, 256>>>(x, row, col);
    k_gemm<FIN><<<MPAD / 64, 256>>>(W0, 0);

    // layer 1: mma.sync tf32 split
    k_agg_init<HID, true><<<(NN * (HID / 4) + 255) / 256, 256>>>(nullptr);
    k_agg_edges<HID, true><<<(NE * (HID / 4) + 255) / 256, 256>>>(nullptr, row, col);
    k_mma<<<MPAD / 128, 256, SM_MMA_BYTES>>>(W1, 1);

    // layer 2: mma.sync tf32 split
    k_agg_init<HID, true><<<(NN * (HID / 4) + 255) / 256, 256>>>(nullptr);
    k_agg_edges<HID, true><<<(NE * (HID / 4) + 255) / 256, 256>>>(nullptr, row, col);
    k_mma<<<MPAD / 128, 256, SM_MMA_BYTES>>>(W2, 2);

    // pool + output
    k_pool<<<(NN * 32 + 255) / 256, 256>>>(batch);
    k_out<<<(NG * NOUT + 255) / 256, 256>>>(Wout, bout, out);
}

// round 8
// speedup vs baseline: 1.2218x; 1.1099x over previous
#include <cuda_runtime.h>
#include <cstdint>

#define NN   200000
#define MPAD 200064          // 1563 * 128
#define NE   800000
#define FIN  32
#define HID  128
#define NG   8192
#define NOUT 5

// ---------------- scratch (device globals; no allocations allowed) ----------
__device__ float g_dinv[NN];
__device__ float g_aggA[(size_t)MPAD * FIN];   // layer-0 aggregation (K=32)
__device__ float g_aggP[(size_t)MPAD * HID];   // layer-1 aggregation
__device__ float g_aggQ[(size_t)MPAD * HID];   // layer-2 aggregation
__device__ float g_h[(size_t)MPAD * HID];      // hs = dinv * relu(bn(...))
__device__ float g_pool[NG * HID];
__device__ float g_cnt[NG];
__device__ float g_scale[3 * HID];
__device__ float g_shift[3 * HID];

// ---------------- helpers ----------------------------------------------------
__device__ __forceinline__ void red_add_v4(float* addr, float4 v) {
    asm volatile("red.global.add.v4.f32 [%0], {%1,%2,%3,%4};"
                 :: "l"(addr), "f"(v.x), "f"(v.y), "f"(v.z), "f"(v.w)
                 : "memory");
}

__device__ __forceinline__ void red_add_v2(float* addr, float x, float y) {
    asm volatile("red.global.add.v2.f32 [%0], {%1,%2};"
                 :: "l"(addr), "f"(x), "f"(y)
                 : "memory");
}

__device__ __forceinline__ float tf32f(float x) {
    uint32_t u;
    asm("cvt.rna.tf32.f32 %0, %1;" : "=r"(u) : "f"(x));
    return __uint_as_float(u);
}

__device__ __forceinline__ void mma_tf32(float* d, const uint32_t* a, const uint32_t* b) {
    asm volatile("mma.sync.aligned.m16n8k8.row.col.f32.tf32.tf32.f32 "
                 "{%0,%1,%2,%3}, {%4,%5,%6,%7}, {%8,%9}, {%0,%1,%2,%3};"
                 : "+f"(d[0]), "+f"(d[1]), "+f"(d[2]), "+f"(d[3])
                 : "r"(a[0]), "r"(a[1]), "r"(a[2]), "r"(a[3]),
                   "r"(b[0]), "r"(b[1]));
}

// ---------------- init / degree / counts -------------------------------------
__global__ void k_zero() {
    int i = blockIdx.x * blockDim.x + threadIdx.x;
    if (i < NN)       g_dinv[i] = 0.f;
    if (i < NG * HID) g_pool[i] = 0.f;
    if (i < NG)       g_cnt[i]  = 0.f;
}

__global__ void k_count(const int* __restrict__ col, const int* __restrict__ batch) {
    int e = blockIdx.x * blockDim.x + threadIdx.x;
    if (e < NE) atomicAdd(&g_dinv[col[e]], 1.0f);
    if (e < NN) atomicAdd(&g_cnt[batch[e]], 1.0f);
}

__global__ void k_dinv() {
    int v = blockIdx.x * blockDim.x + threadIdx.x;
    if (v < NN) g_dinv[v] = rsqrtf(g_dinv[v] + 1.0f);
}

__global__ void k_affine(const float* __restrict__ b, const float* __restrict__ ga,
                         const float* __restrict__ be, const float* __restrict__ me,
                         const float* __restrict__ va, int layer) {
    int c = threadIdx.x;
    if (c < HID) {
        float s = ga[c] * rsqrtf(va[c] + 1e-5f);
        g_scale[layer * HID + c] = s;
        g_shift[layer * HID + c] = (b[c] - me[c]) * s + be[c];
    }
}

// ---------------- layer-0 aggregation (from x) --------------------------------
__global__ void k_agg_init0(const float* __restrict__ x) {
    const int Q = FIN / 4;
    int i = blockIdx.x * blockDim.x + threadIdx.x;
    if (i >= NN * Q) return;
    int v = i / Q;
    float dv = g_dinv[v];
    float c = dv * dv;
    float4 a = ((const float4*)x)[i];
    a.x *= c; a.y *= c; a.z *= c; a.w *= c;
    ((float4*)g_aggA)[i] = a;
}

__global__ void k_agg_edges0(const float* __restrict__ x,
                             const int* __restrict__ row, const int* __restrict__ col) {
    const int Q = FIN / 4;
    int i = blockIdx.x * blockDim.x + threadIdx.x;
    if (i >= NE * Q) return;
    int e = i >> 3;
    int q = i & 7;
    int r = row[e], c = col[e];
    float coef = g_dinv[r] * g_dinv[c];
    float4 v = ((const float4*)x)[r * Q + q];
    v.x *= coef; v.y *= coef; v.z *= coef; v.w *= coef;
    red_add_v4(&g_aggA[(size_t)c * FIN + q * 4], v);
}

// ---------------- HID-layer edge scatter: dst += dinv[c] * hs[r] --------------
template<bool TO_Q>
__global__ void k_agg_edges_hs(const int* __restrict__ row, const int* __restrict__ col) {
    int i = blockIdx.x * blockDim.x + threadIdx.x;
    if (i >= NE * 32) return;
    int e = i >> 5;
    int q = i & 31;
    int r = row[e], c = col[e];
    float coef = g_dinv[c];
    float4 v = *(const float4*)&g_h[(size_t)r * HID + q * 4];
    v.x *= coef; v.y *= coef; v.z *= coef; v.w *= coef;
    float* dst = TO_Q ? g_aggQ : g_aggP;
    red_add_v4(&dst[(size_t)c * HID + q * 4], v);
}

// ---------------- SIMT GEMM (layer 0, K=32) ----------------------------------
// reads g_aggA; epilogue writes hs -> g_h and dinv*hs -> g_aggP
__global__ __launch_bounds__(256)
void k_gemm0(const float* __restrict__ W) {
    __shared__ float sAt[32][68];
    __shared__ float sB[32][128];

    const int tid = threadIdx.x;
    const int tr  = tid >> 5;
    const int tc  = tid & 31;
    const int row0 = blockIdx.x * 64;

    float acc[8][4];
#pragma unroll
    for (int m = 0; m < 8; m++)
#pragma unroll
        for (int n = 0; n < 4; n++) acc[m][n] = 0.f;

    {
#pragma unroll
        for (int i = 0; i < 2; i++) {
            int l  = tid + 256 * i;
            int r  = l >> 3;
            int k4 = (l & 7) * 4;
            float4 a = *(const float4*)&g_aggA[(size_t)(row0 + r) * FIN + k4];
            sAt[k4 + 0][r] = a.x; sAt[k4 + 1][r] = a.y;
            sAt[k4 + 2][r] = a.z; sAt[k4 + 3][r] = a.w;
        }
#pragma unroll
        for (int i = 0; i < 4; i++) {
            int f  = tid + 256 * i;
            int k  = f >> 5;
            int c4 = (f & 31) * 4;
            *(float4*)&sB[k][c4] = *(const float4*)&W[(size_t)k * 128 + c4];
        }
        __syncthreads();

#pragma unroll
        for (int k = 0; k < 32; k++) {
            float4 a0 = *(const float4*)&sAt[k][tr * 8];
            float4 a1 = *(const float4*)&sAt[k][tr * 8 + 4];
            float4 b  = *(const float4*)&sB[k][tc * 4];
            float av[8] = {a0.x, a0.y, a0.z, a0.w, a1.x, a1.y, a1.z, a1.w};
            float bv[4] = {b.x, b.y, b.z, b.w};
#pragma unroll
            for (int m = 0; m < 8; m++)
#pragma unroll
                for (int n = 0; n < 4; n++)
                    acc[m][n] += av[m] * bv[n];
        }
    }

    int colb = tc * 4;
    float4 s = *(const float4*)&g_scale[colb];
    float4 t = *(const float4*)&g_shift[colb];
#pragma unroll
    for (int m = 0; m < 8; m++) {
        int rr = row0 + tr * 8 + m;
        if (rr < NN) {
            float dv = g_dinv[rr];
            float4 o;
            o.x = fmaxf(acc[m][0] * s.x + t.x, 0.f) * dv;
            o.y = fmaxf(acc[m][1] * s.y + t.y, 0.f) * dv;
            o.z = fmaxf(acc[m][2] * s.z + t.z, 0.f) * dv;
            o.w = fmaxf(acc[m][3] * s.w + t.w, 0.f) * dv;
            *(float4*)&g_h[(size_t)rr * 128 + colb] = o;    // hs
            float4 p = {o.x * dv, o.y * dv, o.z * dv, o.w * dv};
            *(float4*)&g_aggP[(size_t)rr * 128 + colb] = p; // self-loop init
        }
    }
}

// ---------------- mma.sync tf32 GEMM (layers 1/2, K=128) ---------------------
// LAST=false: read g_aggP; epilogue writes hs->g_h, dinv*hs->g_aggQ.
// LAST=true : read g_aggQ; epilogue red.adds relu(bn(..)) into g_pool[batch].
#define SA_STRIDE 68
#define SB_STRIDE 136
#define SM_A_FLOATS (128 * SA_STRIDE)
#define SM_B_FLOATS (64 * SB_STRIDE)
#define SM_MMA_BYTES ((SM_A_FLOATS + SM_B_FLOATS) * 4)

template<bool LAST>
__global__ __launch_bounds__(256, 2)
void k_mma(const float* __restrict__ Wm, int layer, const int* __restrict__ batch) {
    extern __shared__ float smem[];
    float* sA = smem;
    float* sB = smem + SM_A_FLOATS;

    const int tid = threadIdx.x;
    const int wid = tid >> 5;
    const int l   = tid & 31;
    const int wr  = wid >> 2;
    const int wc  = wid & 3;
    const size_t row0 = (size_t)blockIdx.x * 128;
    const float* src = LAST ? g_aggQ : g_aggP;

    float acc[4][4][4];
#pragma unroll
    for (int mt = 0; mt < 4; mt++)
#pragma unroll
        for (int nt = 0; nt < 4; nt++)
#pragma unroll
            for (int r = 0; r < 4; r++) acc[mt][nt][r] = 0.f;

    const int lr = l >> 2;
    const int lc = l & 3;

    for (int kc = 0; kc < 2; kc++) {
#pragma unroll
        for (int it = 0; it < 8; it++) {
            int idx = tid + it * 256;
            int r   = idx >> 4;
            int q4  = (idx & 15) * 4;
            float4 a = *(const float4*)&src[(row0 + r) * HID + kc * 64 + q4];
            float* p = &sA[r * SA_STRIDE + q4];
            p[0] = a.x; p[1] = a.y; p[2] = a.z; p[3] = a.w;
        }
#pragma unroll
        for (int it = 0; it < 8; it++) {
            int idx = tid + it * 256;
            int k   = idx >> 5;
            int n4  = (idx & 31) * 4;
            float4 b = *(const float4*)&Wm[(size_t)(kc * 64 + k) * HID + n4];
            float* p = &sB[k * SB_STRIDE + n4];
            p[0] = b.x; p[1] = b.y; p[2] = b.z; p[3] = b.w;
        }
        __syncthreads();

#pragma unroll
        for (int ks = 0; ks < 8; ks++) {
            const int kk = ks * 8;
            uint32_t bh[4][2], bl[4][2];
#pragma unroll
            for (int nt = 0; nt < 4; nt++) {
                int colp = wc * 32 + nt * 8 + lr;
                float b0 = sB[(kk + lc) * SB_STRIDE + colp];
                float b1 = sB[(kk + 4 + lc) * SB_STRIDE + colp];
                float h0 = tf32f(b0), h1 = tf32f(b1);
                bh[nt][0] = __float_as_uint(h0); bl[nt][0] = __float_as_uint(b0 - h0);
                bh[nt][1] = __float_as_uint(h1); bl[nt][1] = __float_as_uint(b1 - h1);
            }
#pragma unroll
            for (int mt = 0; mt < 4; mt++) {
                int rbase = wr * 64 + mt * 16 + lr;
                float a0 = sA[rbase * SA_STRIDE + kk + lc];
                float a1 = sA[(rbase + 8) * SA_STRIDE + kk + lc];
                float a2 = sA[rbase * SA_STRIDE + kk + 4 + lc];
                float a3 = sA[(rbase + 8) * SA_STRIDE + kk + 4 + lc];
                float h0 = tf32f(a0), h1 = tf32f(a1), h2 = tf32f(a2), h3 = tf32f(a3);
                uint32_t ah[4] = {__float_as_uint(h0), __float_as_uint(h1),
                                  __float_as_uint(h2), __float_as_uint(h3)};
                uint32_t al[4] = {__float_as_uint(a0 - h0), __float_as_uint(a1 - h1),
                                  __float_as_uint(a2 - h2), __float_as_uint(a3 - h3)};
#pragma unroll
                for (int nt = 0; nt < 4; nt++) {
                    mma_tf32(acc[mt][nt], ah, bh[nt]);
                    mma_tf32(acc[mt][nt], al, bh[nt]);
                    mma_tf32(acc[mt][nt], ah, bl[nt]);
                }
            }
        }
        __syncthreads();
    }

    // epilogue
    float2 sc[4], sh[4];
#pragma unroll
    for (int nt = 0; nt < 4; nt++) {
        int c = wc * 32 + nt * 8 + 2 * lc;
        sc[nt] = *(const float2*)&g_scale[layer * HID + c];
        sh[nt] = *(const float2*)&g_shift[layer * HID + c];
    }
#pragma unroll
    for (int mt = 0; mt < 4; mt++) {
        size_t r0a = row0 + wr * 64 + mt * 16 + lr;
        size_t r1a = r0a + 8;
        if (LAST) {
            int b0 = (r0a < NN) ? batch[r0a] : -1;
            int b1 = (r1a < NN) ? batch[r1a] : -1;
#pragma unroll
            for (int nt = 0; nt < 4; nt++) {
                int c = wc * 32 + nt * 8 + 2 * lc;
                if (b0 >= 0) {
                    float ox = fmaxf(acc[mt][nt][0] * sc[nt].x + sh[nt].x, 0.f);
                    float oy = fmaxf(acc[mt][nt][1] * sc[nt].y + sh[nt].y, 0.f);
                    red_add_v2(&g_pool[b0 * HID + c], ox, oy);
                }
                if (b1 >= 0) {
                    float ox = fmaxf(acc[mt][nt][2] * sc[nt].x + sh[nt].x, 0.f);
                    float oy = fmaxf(acc[mt][nt][3] * sc[nt].y + sh[nt].y, 0.f);
                    red_add_v2(&g_pool[b1 * HID + c], ox, oy);
                }
            }
        } else {
            float dv0 = (r0a < NN) ? g_dinv[r0a] : 0.f;
            float dv1 = (r1a < NN) ? g_dinv[r1a] : 0.f;
#pragma unroll
            for (int nt = 0; nt < 4; nt++) {
                int c = wc * 32 + nt * 8 + 2 * lc;
                if (r0a < NN) {
                    float hx = fmaxf(acc[mt][nt][0] * sc[nt].x + sh[nt].x, 0.f) * dv0;
                    float hy = fmaxf(acc[mt][nt][1] * sc[nt].y + sh[nt].y, 0.f) * dv0;
                    *(float2*)&g_h[r0a * HID + c]    = {hx, hy};
                    *(float2*)&g_aggQ[r0a * HID + c] = {hx * dv0, hy * dv0};
                }
                if (r1a < NN) {
                    float hx = fmaxf(acc[mt][nt][2] * sc[nt].x + sh[nt].x, 0.f) * dv1;
                    float hy = fmaxf(acc[mt][nt][3] * sc[nt].y + sh[nt].y, 0.f) * dv1;
                    *(float2*)&g_h[r1a * HID + c]    = {hx, hy};
                    *(float2*)&g_aggQ[r1a * HID + c] = {hx * dv1, hy * dv1};
                }
            }
        }
    }
}

// ---------------- output ------------------------------------------------------
__global__ void k_out(const float* __restrict__ Wout, const float* __restrict__ bout,
                      float* __restrict__ out) {
    int i = blockIdx.x * blockDim.x + threadIdx.x;
    if (i >= NG * NOUT) return;
    int g = i / NOUT, o = i - g * NOUT;
    float inv = 1.0f / fmaxf(g_cnt[g], 1.0f);
    const float* p = &g_pool[g * HID];
    float s = 0.f;
#pragma unroll 8
    for (int k = 0; k < HID; k++) s += p[k] * Wout[k * NOUT + o];
    out[i] = s * inv + bout[o];
}

// ---------------- launch -----------------------------------------------------
extern "C" void kernel_launch(void* const* d_in, const int* in_sizes, int n_in,
                              void* d_out, int out_size) {
    const float* x     = (const float*)d_in[0];
    const int*   ei    = (const int*)d_in[1];
    const int*   batch = (const int*)d_in[2];
    const float* W0 = (const float*)d_in[3];
    const float* b0 = (const float*)d_in[4];
    const float* ga0 = (const float*)d_in[5];
    const float* be0 = (const float*)d_in[6];
    const float* me0 = (const float*)d_in[7];
    const float* va0 = (const float*)d_in[8];
    const float* W1 = (const float*)d_in[9];
    const float* b1 = (const float*)d_in[10];
    const float* ga1 = (const float*)d_in[11];
    const float* be1 = (const float*)d_in[12];
    const float* me1 = (const float*)d_in[13];
    const float* va1 = (const float*)d_in[14];
    const float* W2 = (const float*)d_in[15];
    const float* b2 = (const float*)d_in[16];
    const float* ga2 = (const float*)d_in[17];
    const float* be2 = (const float*)d_in[18];
    const float* me2 = (const float*)d_in[19];
    const float* va2 = (const float*)d_in[20];
    const float* Wout = (const float*)d_in[21];
    const float* bout = (const float*)d_in[22];
    float* out = (float*)d_out;

    const int* row = ei;
    const int* col = ei + NE;

    cudaFuncSetAttribute(k_mma<false>, cudaFuncAttributeMaxDynamicSharedMemorySize, SM_MMA_BYTES);
    cudaFuncSetAttribute(k_mma<true>,  cudaFuncAttributeMaxDynamicSharedMemorySize, SM_MMA_BYTES);

    k_zero<<<(NG * HID + 255) / 256, 256>>>();
    k_count<<<(NE + 255) / 256, 256>>>(col, batch);
    k_dinv<<<(NN + 255) / 256, 256>>>();
    k_affine<<<1, 128>>>(b0, ga0, be0, me0, va0, 0);
    k_affine<<<1, 128>>>(b1, ga1, be1, me1, va1, 1);
    k_affine<<<1, 128>>>(b2, ga2, be2, me2, va2, 2);

    // layer 0: aggregate x into aggA, GEMM -> hs + aggP init
    k_agg_init0<<<(NN * (FIN / 4) + 255) / 256, 256>>>(x);
    k_agg_edges0<<<(NE * (FIN / 4) + 255) / 256, 256>>>(x, row, col);
    k_gemm0<<<MPAD / 64, 256>>>(W0);

    // layer 1: edges add dinv[c]*hs[r] into aggP; mma -> hs + aggQ init
    k_agg_edges_hs<false><<<(NE * 32 + 255) / 256, 256>>>(row, col);
    k_mma<false><<<MPAD / 128, 256, SM_MMA_BYTES>>>(W1, 1, batch);

    // layer 2: edges into aggQ; mma -> pool atomics
    k_agg_edges_hs<true><<<(NE * 32 + 255) / 256, 256>>>(row, col);
    k_mma<true><<<MPAD / 128, 256, SM_MMA_BYTES>>>(W2, 2, batch);

    // output
    k_out<<<(NG * NOUT + 255) / 256, 256>>>(Wout, bout, out);
}